// round 16
// baseline (speedup 1.0000x reference)
#include <cuda_runtime.h>
#include <cuda_bf16.h>

// Problem constants: IN=4, H=30, OUT=1, N_UNIT=100, B=262144
#define NU    100
#define HH    30
#define NT    256          // threads per block
#define GRID  444          // 148 SMs x 3 blocks/SM = one exact wave
#define NBLO  590          // rows per block (184 blocks get 591)
#define NBHI  591
#define MAXNB 591

typedef unsigned long long u64;

// ---- packed f32x2 helpers (sm_103a) ----
__device__ __forceinline__ u64 ffma2(u64 a, u64 b, u64 c) {
    u64 d;
    asm("fma.rn.f32x2 %0, %1, %2, %3;" : "=l"(d) : "l"(a), "l"(b), "l"(c));
    return d;
}
__device__ __forceinline__ u64 pack2(float x, float y) {
    u64 d;
    asm("mov.b64 %0, {%1, %2};" : "=l"(d) : "f"(x), "f"(y));
    return d;
}
__device__ __forceinline__ float2 unpack2(u64 a) {
    float2 f;
    asm("mov.b64 {%0, %1}, %2;" : "=f"(f.x), "=f"(f.y) : "l"(a));
    return f;
}
__device__ __forceinline__ u64 relu2(u64 a) {
    float2 f = unpack2(a);
    return pack2(fmaxf(f.x, 0.0f), fmaxf(f.y, 0.0f));
}

// ---------------------------------------------------------------------------
// Exact-balance persistent kernel: 444 blocks (one full wave), block b owns
// 590/591 contiguous rows. RPT=3, 3-way k-split (5 k-pairs live per pass ->
// 30 acc regs). W2 stored per-pass as 12-float aligned segments. Dense
// register-cached store epilogue.
// ---------------------------------------------------------------------------
__global__ __launch_bounds__(NT, 3)
void mlp_dispatch_kernel(const float4* __restrict__ x,     // [B,4] as float4
                         const float*  __restrict__ Cost,  // [100]
                         const float*  __restrict__ Pmax,  // [100]
                         const float*  __restrict__ Pd,    // [100]
                         const float*  __restrict__ wcap,  // [1]
                         const float*  __restrict__ W1,    // [4,30]
                         const float*  __restrict__ b1,    // [30]
                         const float*  __restrict__ W2,    // [30,30]
                         const float*  __restrict__ b2,    // [30]
                         const float*  __restrict__ W3,    // [30,1]
                         const float*  __restrict__ b3,    // [1]
                         float*        __restrict__ out)   // [B,100]
{
    __shared__ alignas(16) float4 sW1t[HH];        // sW1t[i] = W1[0..3][i]
    __shared__ alignas(16) float  sb1[HH];
    __shared__ alignas(16) float  sW2s[3 * HH * 12]; // [pass][i][12]; c>=10 -> 0
    __shared__ alignas(16) float  sb2s[3 * 12];      // [pass][12], pad 0
    __shared__ alignas(16) float  sW3s[3 * 12];      // [pass][12], pad 0
    __shared__ alignas(16) float  sCost[NU];
    __shared__ alignas(16) float  sCum[NU];
    __shared__ alignas(16) float  sPmax[NU];
    __shared__ alignas(16) float  sTd[MAXNB + 1];
    __shared__ float sB3, sWc, sSum;

    const int tid = threadIdx.x;
    const int b   = blockIdx.x;
    const int nb    = NBLO + (b < 184 ? 1 : 0);
    const long start = (long)NBLO * b + min(b, 184);

    // ---- Stage params ----
    // W2 per-pass segments: pass p, unit i, col c -> W2[i][10p + c] (c<10)
    for (int idx = tid; idx < 3 * HH * 12; idx += NT) {
        int p = idx / (HH * 12);
        int rem = idx - p * (HH * 12);
        int i = rem / 12, c = rem - (rem / 12) * 12;
        int k = 10 * p + c;
        sW2s[idx] = (c < 10 && k < HH) ? W2[i * HH + k] : 0.0f;
    }
    if (tid < 36) {
        int p = tid / 12, c = tid - (tid / 12) * 12;
        int k = 10 * p + c;
        sb2s[tid] = (c < 10 && k < HH) ? b2[k] : 0.0f;
        sW3s[tid] = (c < 10 && k < HH) ? W3[k] : 0.0f;
    }
    if (tid >= 64 && tid < 64 + HH) {
        int i = tid - 64;
        sW1t[i] = make_float4(W1[0 * HH + i], W1[1 * HH + i],
                              W1[2 * HH + i], W1[3 * HH + i]);
        sb1[i] = b1[i];
    }
    if (tid < NU) { sCost[tid] = Cost[tid]; sPmax[tid] = Pmax[tid]; }
    if (tid == 0) { sB3 = b3[0]; sWc = wcap[0]; }
    if (tid >= NT - 32) {          // last warp: parallel sum(Pd)
        int l = tid - (NT - 32);
        float s = 0.0f;
        for (int j = l; j < NU; j += 32) s += Pd[j];
        #pragma unroll
        for (int o = 16; o > 0; o >>= 1)
            s += __shfl_xor_sync(0xFFFFFFFFu, s, o);
        if (l == 0) sSum = s;
    }
    __syncthreads();

    // ---- Merit order (stable argsort closed form), per original unit ----
    if (tid < NU) {
        const float cj = sCost[tid];
        float cum = 0.0f;
        #pragma unroll 4
        for (int k = 0; k < NU; k++) {
            float ck = sCost[k];
            bool cheaper = (ck < cj) || (ck == cj && k < tid);
            if (cheaper) cum += sPmax[k];
        }
        sCum[tid] = cum;
    }

    // ---- this thread's up-to-3 rows (local ids 3t..3t+2), predicated ----
    const int r0l = 3 * tid;
    const bool a0 = (r0l     < nb);
    const bool a1 = (r0l + 1 < nb);
    const bool a2 = (r0l + 2 < nb);
    const float4 xr0 = a0 ? x[start + r0l]     : make_float4(0.f, 0.f, 0.f, 0.f);
    const float4 xr1 = a1 ? x[start + r0l + 1] : make_float4(0.f, 0.f, 0.f, 0.f);
    const float4 xr2 = a2 ? x[start + r0l + 2] : make_float4(0.f, 0.f, 0.f, 0.f);

    // ---- MLP: three k-third passes; 5 packed k-pairs live per row ----
    u64 yp0 = pack2(sB3, 0.0f);
    u64 yp1 = pack2(sB3, 0.0f);
    u64 yp2 = pack2(sB3, 0.0f);
    for (int p = 0; p < 3; p++) {                 // rolled (I$)
        u64 acc0[5], acc1[5], acc2[5];
        #pragma unroll
        for (int q = 0; q < 5; q++) {
            u64 bp = *reinterpret_cast<const u64*>(&sb2s[12 * p + 2 * q]);
            acc0[q] = bp; acc1[q] = bp; acc2[q] = bp;
        }
        const float* wbase = &sW2s[p * (HH * 12)];
        #pragma unroll
        for (int i = 0; i < HH; i++) {
            const float4 w1 = sW1t[i];
            const float  bb = sb1[i];
            float v0 = bb, v1 = bb, v2 = bb;
            v0 = fmaf(xr0.x, w1.x, v0); v1 = fmaf(xr1.x, w1.x, v1); v2 = fmaf(xr2.x, w1.x, v2);
            v0 = fmaf(xr0.y, w1.y, v0); v1 = fmaf(xr1.y, w1.y, v1); v2 = fmaf(xr2.y, w1.y, v2);
            v0 = fmaf(xr0.z, w1.z, v0); v1 = fmaf(xr1.z, w1.z, v1); v2 = fmaf(xr2.z, w1.z, v2);
            v0 = fmaf(xr0.w, w1.w, v0); v1 = fmaf(xr1.w, w1.w, v1); v2 = fmaf(xr2.w, w1.w, v2);
            const float h0 = fmaxf(v0, 0.0f);
            const float h1 = fmaxf(v1, 0.0f);
            const float h2 = fmaxf(v2, 0.0f);
            const u64 h0d = pack2(h0, h0);
            const u64 h1d = pack2(h1, h1);
            const u64 h2d = pack2(h2, h2);

            // 12 floats (48B, 16B-aligned) = 6 k-pair operands; last is zero pad
            const float* wrow = wbase + i * 12;
            ulonglong2 wva = *reinterpret_cast<const ulonglong2*>(wrow);      // pairs 0,1
            ulonglong2 wvb = *reinterpret_cast<const ulonglong2*>(wrow + 4);  // pairs 2,3
            u64        wvc = *reinterpret_cast<const u64*>(wrow + 8);         // pair 4
            acc0[0] = ffma2(h0d, wva.x, acc0[0]);
            acc1[0] = ffma2(h1d, wva.x, acc1[0]);
            acc2[0] = ffma2(h2d, wva.x, acc2[0]);
            acc0[1] = ffma2(h0d, wva.y, acc0[1]);
            acc1[1] = ffma2(h1d, wva.y, acc1[1]);
            acc2[1] = ffma2(h2d, wva.y, acc2[1]);
            acc0[2] = ffma2(h0d, wvb.x, acc0[2]);
            acc1[2] = ffma2(h1d, wvb.x, acc1[2]);
            acc2[2] = ffma2(h2d, wvb.x, acc2[2]);
            acc0[3] = ffma2(h0d, wvb.y, acc0[3]);
            acc1[3] = ffma2(h1d, wvb.y, acc1[3]);
            acc2[3] = ffma2(h2d, wvb.y, acc2[3]);
            acc0[4] = ffma2(h0d, wvc,  acc0[4]);
            acc1[4] = ffma2(h1d, wvc,  acc1[4]);
            acc2[4] = ffma2(h2d, wvc,  acc2[4]);
        }
        // fold this k-third into the output dots
        #pragma unroll
        for (int q = 0; q < 5; q++) {
            u64 w3p = *reinterpret_cast<const u64*>(&sW3s[12 * p + 2 * q]);
            yp0 = ffma2(relu2(acc0[q]), w3p, yp0);
            yp1 = ffma2(relu2(acc1[q]), w3p, yp1);
            yp2 = ffma2(relu2(acc2[q]), w3p, yp2);
        }
    }
    {
        const float2 y0 = unpack2(yp0);
        const float2 y1 = unpack2(yp1);
        const float2 y2 = unpack2(yp2);
        if (a0) sTd[r0l]     = sSum - sWc * (y0.x + y0.y);
        if (a1) sTd[r0l + 1] = sSum - sWc * (y1.x + y1.y);
        if (a2) sTd[r0l + 2] = sSum - sWc * (y2.x + y2.y);
    }
    __syncthreads();

    // ---- dispatch + store: register-cached cu/pm per fixed vec4-column ----
    // 250 active threads: g = t%25 (column group), r0 = t/25 (0..9).
    if (tid < 250) {
        const int g  = tid % 25;
        const int rr = tid / 25;
        const float4 cu4 = *reinterpret_cast<const float4*>(sCum  + 4 * g);
        const float4 pm4 = *reinterpret_cast<const float4*>(sPmax + 4 * g);
        float4* outv = reinterpret_cast<float4*>(out + start * NU);
        #pragma unroll 4
        for (int it = 0; it < 60; it++) {        // ceil(591/10) = 60
            const int r = rr + 10 * it;
            if (r < nb) {
                const float t = sTd[r];
                float4 pq;
                pq.x = fminf(fmaxf(t - cu4.x, 0.0f), pm4.x);
                pq.y = fminf(fmaxf(t - cu4.y, 0.0f), pm4.y);
                pq.z = fminf(fmaxf(t - cu4.z, 0.0f), pm4.z);
                pq.w = fminf(fmaxf(t - cu4.w, 0.0f), pm4.w);
                outv[r * 25 + g] = pq;
            }
        }
    }
}

// ---------------------------------------------------------------------------
// Launch. Input order: x, Cost, Pmax, Pd, w_capacity, W1, b1, W2, b2, W3, b3
// ---------------------------------------------------------------------------
extern "C" void kernel_launch(void* const* d_in, const int* in_sizes, int n_in,
                              void* d_out, int out_size) {
    const float* x     = (const float*)d_in[0];
    const float* Cost  = (const float*)d_in[1];
    const float* Pmax  = (const float*)d_in[2];
    const float* Pd    = (const float*)d_in[3];
    const float* wcap  = (const float*)d_in[4];
    const float* W1    = (const float*)d_in[5];
    const float* b1    = (const float*)d_in[6];
    const float* W2    = (const float*)d_in[7];
    const float* b2    = (const float*)d_in[8];
    const float* W3    = (const float*)d_in[9];
    const float* b3    = (const float*)d_in[10];
    float* out = (float*)d_out;

    mlp_dispatch_kernel<<<GRID, NT>>>(
        (const float4*)x, Cost, Pmax, Pd, wcap, W1, b1, W2, b2, W3, b3, out);
}

// round 17
// speedup vs baseline: 1.4077x; 1.4077x over previous
#include <cuda_runtime.h>
#include <cuda_bf16.h>

// Problem constants: IN=4, H=30, OUT=1, N_UNIT=100, B=262144
#define NU    100
#define HH    30
#define NT    256          // threads per block
#define RPT   2            // rows per thread
#define RPB   (NT * RPT)   // 512 rows per block

typedef unsigned long long u64;

// ---- packed f32x2 helpers (sm_103a) ----
__device__ __forceinline__ u64 ffma2(u64 a, u64 b, u64 c) {
    u64 d;
    asm("fma.rn.f32x2 %0, %1, %2, %3;" : "=l"(d) : "l"(a), "l"(b), "l"(c));
    return d;
}
__device__ __forceinline__ u64 pack2(float x, float y) {
    u64 d;
    asm("mov.b64 %0, {%1, %2};" : "=l"(d) : "f"(x), "f"(y));
    return d;
}
__device__ __forceinline__ float2 unpack2(u64 a) {
    float2 f;
    asm("mov.b64 {%0, %1}, %2;" : "=f"(f.x), "=f"(f.y) : "l"(a));
    return f;
}
__device__ __forceinline__ u64 relu2(u64 a) {
    float2 f = unpack2(a);
    return pack2(fmaxf(f.x, 0.0f), fmaxf(f.y, 0.0f));
}

// ---------------------------------------------------------------------------
// R9 structure (proven best): per-block merit-order setup; 2 rows/thread MLP
// with scalar layer-1 (float4 W1) and 2-pass k-split layer-2 (8 k-pairs live
// -> 32 acc regs); register-cached coalesced store epilogue.
// Micro-fixes: early x prefetch, 250-thread epilogue, streaming stores.
// ---------------------------------------------------------------------------
__global__ __launch_bounds__(NT, 3)
void mlp_dispatch_kernel(const float4* __restrict__ x,     // [B,4] as float4
                         const float*  __restrict__ Cost,  // [100]
                         const float*  __restrict__ Pmax,  // [100]
                         const float*  __restrict__ Pd,    // [100]
                         const float*  __restrict__ wcap,  // [1]
                         const float*  __restrict__ W1,    // [4,30]
                         const float*  __restrict__ b1,    // [30]
                         const float*  __restrict__ W2,    // [30,30]
                         const float*  __restrict__ b2,    // [30]
                         const float*  __restrict__ W3,    // [30,1]
                         const float*  __restrict__ b3,    // [1]
                         float*        __restrict__ out)   // [B,100]
{
    __shared__ alignas(16) float4 sW1t[HH];      // sW1t[i] = W1[0..3][i] (transposed)
    __shared__ alignas(16) float  sb1[HH];
    __shared__ alignas(16) float  sW2[HH * 32];  // rows padded to 32 floats (zeros)
    __shared__ alignas(16) float  sb2[32];       // padded with zeros
    __shared__ alignas(16) float  sW3[32];       // padded with zeros
    __shared__ alignas(16) float  sCost[NU];
    __shared__ alignas(16) float  sCum[NU];
    __shared__ alignas(16) float  sPmax[NU];
    __shared__ alignas(16) float  sTd[RPB];
    __shared__ float sB3, sWc, sSum;

    const int tid = threadIdx.x;

    // ---- prefetch this thread's 2 rows FIRST (DRAM latency hidden by prologue)
    const long base = (long)blockIdx.x * RPB + 2 * tid;
    const float4 x0 = x[base];
    const float4 x1 = x[base + 1];

    // ---- Stage params ----
    for (int i = tid; i < HH * 32; i += NT) {
        int r = i >> 5, c = i & 31;
        sW2[i] = (c < HH) ? W2[r * HH + c] : 0.0f;
    }
    if (tid < 32) {
        sb2[tid] = (tid < HH) ? b2[tid] : 0.0f;
        sW3[tid] = (tid < HH) ? W3[tid] : 0.0f;
    }
    if (tid >= 32 && tid < 32 + HH) {
        int i = tid - 32;
        sW1t[i] = make_float4(W1[0 * HH + i], W1[1 * HH + i],
                              W1[2 * HH + i], W1[3 * HH + i]);
        sb1[i] = b1[i];
    }
    if (tid < NU) { sCost[tid] = Cost[tid]; sPmax[tid] = Pmax[tid]; }
    if (tid == 0) { sB3 = b3[0]; sWc = wcap[0]; }
    if (tid >= NT - 32) {          // last warp: parallel sum(Pd)
        int l = tid - (NT - 32);
        float s = 0.0f;
        for (int j = l; j < NU; j += 32) s += Pd[j];
        #pragma unroll
        for (int o = 16; o > 0; o >>= 1)
            s += __shfl_xor_sync(0xFFFFFFFFu, s, o);
        if (l == 0) sSum = s;
    }
    __syncthreads();

    // ---- Merit order (stable argsort closed form), per original unit ----
    if (tid < NU) {
        const float cj = sCost[tid];
        float cum = 0.0f;
        #pragma unroll 4
        for (int k = 0; k < NU; k++) {
            float ck = sCost[k];
            bool cheaper = (ck < cj) || (ck == cj && k < tid);
            if (cheaper) cum += sPmax[k];
        }
        sCum[tid] = cum;
    }

    __syncthreads();

    // ---- MLP: two k-half passes; 8 packed k-pairs live per pass per row ----
    u64 yp0 = pack2(sB3, 0.0f);
    u64 yp1 = pack2(sB3, 0.0f);
    #pragma unroll
    for (int p = 0; p < 2; p++) {
        u64 acc0[8], acc1[8];
        #pragma unroll
        for (int q = 0; q < 8; q++) {
            u64 bp = *reinterpret_cast<const u64*>(&sb2[16 * p + 2 * q]);
            acc0[q] = bp;
            acc1[q] = bp;
        }
        #pragma unroll
        for (int i = 0; i < HH; i++) {
            // layer-1 unit i for both rows (scalar, float4 weight load)
            const float4 w1 = sW1t[i];
            const float  bb = sb1[i];
            float a0 = bb, a1 = bb;
            a0 = fmaf(x0.x, w1.x, a0);  a1 = fmaf(x1.x, w1.x, a1);
            a0 = fmaf(x0.y, w1.y, a0);  a1 = fmaf(x1.y, w1.y, a1);
            a0 = fmaf(x0.z, w1.z, a0);  a1 = fmaf(x1.z, w1.z, a1);
            a0 = fmaf(x0.w, w1.w, a0);  a1 = fmaf(x1.w, w1.w, a1);
            const float h0 = fmaxf(a0, 0.0f);
            const float h1 = fmaxf(a1, 0.0f);
            const u64 h0d = pack2(h0, h0);
            const u64 h1d = pack2(h1, h1);

            // this pass's 16 floats of W2 row i (4x LDS.128, shared by 2 rows)
            const float* wrow = &sW2[i * 32 + 16 * p];
            #pragma unroll
            for (int ql = 0; ql < 4; ql++) {
                ulonglong2 wv = *reinterpret_cast<const ulonglong2*>(wrow + 4 * ql);
                acc0[2 * ql]     = ffma2(h0d, wv.x, acc0[2 * ql]);
                acc1[2 * ql]     = ffma2(h1d, wv.x, acc1[2 * ql]);
                acc0[2 * ql + 1] = ffma2(h0d, wv.y, acc0[2 * ql + 1]);
                acc1[2 * ql + 1] = ffma2(h1d, wv.y, acc1[2 * ql + 1]);
            }
        }
        // fold this k-half into the output dot (padded W3 zeros are harmless)
        #pragma unroll
        for (int q = 0; q < 8; q++) {
            u64 w3p = *reinterpret_cast<const u64*>(&sW3[16 * p + 2 * q]);
            yp0 = ffma2(relu2(acc0[q]), w3p, yp0);
            yp1 = ffma2(relu2(acc1[q]), w3p, yp1);
        }
    }
    const float2 y0 = unpack2(yp0);
    const float2 y1 = unpack2(yp1);

    sTd[2 * tid]     = sSum - sWc * (y0.x + y0.y);
    sTd[2 * tid + 1] = sSum - sWc * (y1.x + y1.y);
    __syncthreads();

    // ---- dispatch + store: register-cached cu/pm per fixed vec4-column ----
    // 250 active threads: g = t%25 (column group), r0 = t/25 (0..9).
    // Streaming (evict-first) stores: the 105MB output is never re-read.
    if (tid < 250) {
        const int g  = tid % 25;
        const int r0 = tid / 25;
        const float4 cu4 = *reinterpret_cast<const float4*>(sCum  + 4 * g);
        const float4 pm4 = *reinterpret_cast<const float4*>(sPmax + 4 * g);
        float4* outv = reinterpret_cast<float4*>(out + (size_t)blockIdx.x * RPB * NU);
        #pragma unroll 4
        for (int it = 0; it < 52; it++) {        // 512 rows, 10 rows per iter
            const int r = r0 + 10 * it;
            if (r < RPB) {
                const float t = sTd[r];
                float4 pq;
                pq.x = fminf(fmaxf(t - cu4.x, 0.0f), pm4.x);
                pq.y = fminf(fmaxf(t - cu4.y, 0.0f), pm4.y);
                pq.z = fminf(fmaxf(t - cu4.z, 0.0f), pm4.z);
                pq.w = fminf(fmaxf(t - cu4.w, 0.0f), pm4.w);
                __stcs(&outv[r * 25 + g], pq);
            }
        }
    }
}

// ---------------------------------------------------------------------------
// Launch. Input order: x, Cost, Pmax, Pd, w_capacity, W1, b1, W2, b2, W3, b3
// ---------------------------------------------------------------------------
extern "C" void kernel_launch(void* const* d_in, const int* in_sizes, int n_in,
                              void* d_out, int out_size) {
    const float* x     = (const float*)d_in[0];
    const float* Cost  = (const float*)d_in[1];
    const float* Pmax  = (const float*)d_in[2];
    const float* Pd    = (const float*)d_in[3];
    const float* wcap  = (const float*)d_in[4];
    const float* W1    = (const float*)d_in[5];
    const float* b1    = (const float*)d_in[6];
    const float* W2    = (const float*)d_in[7];
    const float* b2    = (const float*)d_in[8];
    const float* W3    = (const float*)d_in[9];
    const float* b3    = (const float*)d_in[10];
    float* out = (float*)d_out;

    const int B = in_sizes[0] / 4;      // x is [B, 4]
    const int blocks = B / RPB;         // 262144 / 512 = 512

    mlp_dispatch_kernel<<<blocks, NT>>>(
        (const float4*)x, Cost, Pmax, Pd, wcap, W1, b1, W2, b2, W3, b3, out);
}